// round 3
// baseline (speedup 1.0000x reference)
#include <cuda_runtime.h>
#include <math.h>

// ---------------- problem constants ----------------
#define NTOK   4096      // QLEN*B
#define RTOK   8192      // RLEN*B
#define DMODEL 1024
#define NHEAD  16
#define DHEAD  64
#define DFF    4096

// ---------------- scratch (__device__ globals; allocation-free) ----------------
__device__ float g_q  [4096 * 1024];
__device__ float g_k  [4096 * 1024];
__device__ float g_v  [4096 * 1024];
__device__ float g_kr [8192 * 1024];
__device__ float g_ef [4096 * 16 * 2];
__device__ float g_s  [67108864];          // [64 (b,n)] x [1024 x 1024] scores->probs in place
__device__ float g_av [4096 * 1024];
__device__ float g_pre[4096 * 1024];
__device__ float g_o1 [4096 * 1024];
__device__ float g_ffh[4096 * 4096];
__device__ float g_p2 [4096 * 1024];

__device__ __forceinline__ float gelu_exact(float x) {
    return 0.5f * x * (1.0f + erff(x * 0.70710678118654752f));
}

// ---------------- generic tiled fp32 GEMM ----------------
// C[M,N] = A[M,K] @ B  (B is [K,N] row-major, or [N,K] if TRANSB)
// batched over blockIdx.z with z = zb*16 + zn and per-operand (zb, zn) strides.
// EPI: 0 none, 1 bias+GELU(exact), 2 +residual, 3 bias+residual
// causal!=0: K-loop truncated at row0+BM (A rows zero beyond the diagonal).
template<int BM, int BN, int BK, int TM, int TN, bool TRANSB, int EPI>
__global__ __launch_bounds__((BM / TM) * (BN / TN))
void gemm_k(const float* __restrict__ A, const float* __restrict__ B,
            float* __restrict__ C, const float* __restrict__ bias,
            const float* __restrict__ R,
            int M, int N, int K, int lda, int ldb, int ldc, int ldr,
            long long sAb, long long sAn, long long sBb, long long sBn,
            long long sCb, long long sCn, int causal)
{
    constexpr int THREADS = (BM / TM) * (BN / TN);
    __shared__ float As[BK][BM + 4];
    __shared__ float Bs[BK][BN + 4];

    const int tid = threadIdx.x;
    const int tx  = tid % (BN / TN);
    const int ty  = tid / (BN / TN);
    const int zb  = blockIdx.z >> 4, zn = blockIdx.z & 15;
    const float* Ap = A + zb * sAb + zn * sAn;
    const float* Bp = B + zb * sBb + zn * sBn;
    float*       Cp = C + zb * sCb + zn * sCn;

    const int row0 = blockIdx.y * BM;
    const int col0 = blockIdx.x * BN;
    const int kEnd = causal ? ((row0 + BM < K) ? (row0 + BM) : K) : K;

    float acc[TM][TN];
    #pragma unroll
    for (int i = 0; i < TM; i++)
        #pragma unroll
        for (int j = 0; j < TN; j++) acc[i][j] = 0.0f;

    for (int kt = 0; kt < kEnd; kt += BK) {
        #pragma unroll
        for (int e = tid; e < BM * BK; e += THREADS) {
            int m = e / BK, kk = e % BK;
            As[kk][m] = Ap[(long long)(row0 + m) * lda + (kt + kk)];
        }
        if (!TRANSB) {
            #pragma unroll
            for (int e = tid; e < BK * BN; e += THREADS) {
                int kk = e / BN, nn = e % BN;
                Bs[kk][nn] = Bp[(long long)(kt + kk) * ldb + (col0 + nn)];
            }
        } else {
            #pragma unroll
            for (int e = tid; e < BK * BN; e += THREADS) {
                int nn = e / BK, kk = e % BK;
                Bs[kk][nn] = Bp[(long long)(col0 + nn) * ldb + (kt + kk)];
            }
        }
        __syncthreads();
        #pragma unroll
        for (int kk = 0; kk < BK; kk++) {
            float a[TM], bv[TN];
            #pragma unroll
            for (int i = 0; i < TM; i++) a[i] = As[kk][ty * TM + i];
            #pragma unroll
            for (int j = 0; j < TN; j++) bv[j] = Bs[kk][tx * TN + j];
            #pragma unroll
            for (int i = 0; i < TM; i++)
                #pragma unroll
                for (int j = 0; j < TN; j++)
                    acc[i][j] += a[i] * bv[j];
        }
        __syncthreads();
    }

    #pragma unroll
    for (int i = 0; i < TM; i++) {
        int r_ = row0 + ty * TM + i;
        #pragma unroll
        for (int j = 0; j < TN; j++) {
            int c_ = col0 + tx * TN + j;
            if (r_ < M && c_ < N) {
                float v = acc[i][j];
                if (EPI == 1) v = gelu_exact(v + bias[c_]);
                if (EPI == 2) v += R[(long long)r_ * ldr + c_];
                if (EPI == 3) v += bias[c_] + R[(long long)r_ * ldr + c_];
                Cp[(long long)r_ * ldc + c_] = v;
            }
        }
    }
}

// ---------------- ef precompute: ef[t,n,s] = sum_d (q[t,n,d]+r_s_bias[n,d])*seg_embed[s,n,d]
__global__ void ef_kernel(const float* __restrict__ q, const float* __restrict__ rsb,
                          const float* __restrict__ se, float* __restrict__ ef)
{
    const int pair = blockIdx.x * 8 + (threadIdx.x >> 5);  // 65536 (t,n) pairs
    const int lane = threadIdx.x & 31;
    const int t = pair >> 4, n = pair & 15;
    const float* qp = q + (long long)t * 1024 + n * 64;
    float e0 = 0.f, e1 = 0.f;
    #pragma unroll
    for (int d = lane; d < 64; d += 32) {
        float qv = qp[d] + rsb[n * 64 + d];
        e0 += qv * se[n * 64 + d];
        e1 += qv * se[1024 + n * 64 + d];
    }
    #pragma unroll
    for (int o = 16; o; o >>= 1) {
        e0 += __shfl_xor_sync(0xffffffffu, e0, o);
        e1 += __shfl_xor_sync(0xffffffffu, e1, o);
    }
    if (lane == 0) {
        ef[((long long)t * 16 + n) * 2]     = e0;
        ef[((long long)t * 16 + n) * 2 + 1] = e1;
    }
}

// ---------------- fused score kernel: (ac + bd(rel-shift) + ef)*SCALE - 1e30*mask ----------------
// One block = 64x64 tile of scores for one (b,n). bd computed via 127-row k_r halo:
// bd[i,j] = (q_i + r_r_bias) . k_r[j - i + 1024]
static const int SCORE_SMEM = (64 * 68 * 2 + 64 * 132 + 64 * 3) * 4;  // 69376 B

__global__ __launch_bounds__(256)
void score_kernel(const float* __restrict__ q, const float* __restrict__ k,
                  const float* __restrict__ kr,
                  const float* __restrict__ rwb, const float* __restrict__ rrb,
                  const float* __restrict__ ef, const float* __restrict__ segm,
                  const float* __restrict__ msk, float* __restrict__ S)
{
    const int j0 = blockIdx.x * 64, i0 = blockIdx.y * 64;
    const int z = blockIdx.z, b = z >> 4, n = z & 15;
    const long long sbase = (long long)z * 1048576ll;
    const int tid = threadIdx.x;

    if (j0 > i0) {  // fully-masked tile (causal mask from setup): exp() underflows to 0
        for (int e = tid; e < 4096; e += 256) {
            int ii = e >> 6, jj = e & 63;
            S[sbase + (long long)(i0 + ii) * 1024 + (j0 + jj)] = -1e30f;
        }
        return;
    }

    extern __shared__ float sm[];
    float* Qt   = sm;               // [64 d][68] q + r_w_bias, d-major
    float* Kt   = Qt + 64 * 68;     // [64 d][68]
    float* Krt  = Kt + 64 * 68;     // [64 d][132] 127-row k_r halo
    float* dbs  = Krt + 64 * 132;   // [64] r_r_bias - r_w_bias
    float* efs0 = dbs + 64;         // [64]
    float* efs1 = efs0 + 64;        // [64]

    const float* qb  = q  + b * 1024 + n * 64;
    const float* kb  = k  + b * 1024 + n * 64;
    const float* krb = kr + b * 1024 + n * 64;

    for (int e = tid; e < 4096; e += 256) {
        int row = e >> 6, d = e & 63;
        Qt[d * 68 + row] = qb[(long long)(i0 + row) * 4096 + d] + rwb[n * 64 + d];
        Kt[d * 68 + row] = kb[(long long)(j0 + row) * 4096 + d];
    }
    const int rel0 = j0 - i0 + 1024 - 63;  // in [1, 1024] for unmasked tiles
    for (int e = tid; e < 127 * 64; e += 256) {
        int row = e >> 6, d = e & 63;
        Krt[d * 132 + row] = krb[(long long)(rel0 + row) * 4096 + d];
    }
    if (tid < 64) {
        dbs[tid] = rrb[n * 64 + tid] - rwb[n * 64 + tid];
        int t = (i0 + tid) * 4 + b;
        efs0[tid] = ef[((long long)t * 16 + n) * 2];
        efs1[tid] = ef[((long long)t * 16 + n) * 2 + 1];
    }
    __syncthreads();

    const int tx = tid & 15, ty = tid >> 4;
    const int ib = ty * 4, jb = tx * 4;
    const int r0 = jb - ib + 60;  // halo index base; in [0, 120], +6 max = 126

    float ac[4][4] = {}, bd[4][4] = {};
    #pragma unroll 4
    for (int kk = 0; kk < 64; kk++) {
        float db = dbs[kk];
        float qa[4], kv[4], krv[7];
        #pragma unroll
        for (int a = 0; a < 4; a++) qa[a] = Qt[kk * 68 + ib + a];
        #pragma unroll
        for (int c = 0; c < 4; c++) kv[c] = Kt[kk * 68 + jb + c];
        #pragma unroll
        for (int m = 0; m < 7; m++) krv[m] = Krt[kk * 132 + r0 + m];
        #pragma unroll
        for (int a = 0; a < 4; a++) {
            float qd = qa[a] + db;
            #pragma unroll
            for (int c = 0; c < 4; c++) {
                ac[a][c] += qa[a] * kv[c];
                bd[a][c] += qd * krv[c - a + 3];
            }
        }
    }

    #pragma unroll
    for (int a = 0; a < 4; a++) {
        int i = i0 + ib + a;
        float e0 = efs0[ib + a], e1 = efs1[ib + a];
        #pragma unroll
        for (int c = 0; c < 4; c++) {
            int j = j0 + jb + c;
            long long mi = ((long long)i * 1024 + j) * 4 + b;
            float seg1 = segm[mi * 2 + 1];           // one-hot -> ef0 + seg1*(ef1-ef0)
            float mv   = msk[mi];
            S[sbase + (long long)i * 1024 + j] =
                (ac[a][c] + bd[a][c] + e0 + seg1 * (e1 - e0)) * 0.125f - 1e30f * mv;
        }
    }
}

// ---------------- in-place softmax over j (warp per row, float4) ----------------
__global__ void softmax_kernel(float* __restrict__ S)
{
    const int row  = blockIdx.x * 8 + (threadIdx.x >> 5);  // 65536 rows
    const int lane = threadIdx.x & 31;
    float4* p = (float4*)(S + (long long)row * 1024);
    float4 v[8];
    float mx = -3.4e38f;
    #pragma unroll
    for (int kk = 0; kk < 8; kk++) {
        v[kk] = p[lane + 32 * kk];
        mx = fmaxf(mx, fmaxf(fmaxf(v[kk].x, v[kk].y), fmaxf(v[kk].z, v[kk].w)));
    }
    #pragma unroll
    for (int o = 16; o; o >>= 1) mx = fmaxf(mx, __shfl_xor_sync(0xffffffffu, mx, o));
    float s = 0.f;
    #pragma unroll
    for (int kk = 0; kk < 8; kk++) {
        v[kk].x = expf(v[kk].x - mx); v[kk].y = expf(v[kk].y - mx);
        v[kk].z = expf(v[kk].z - mx); v[kk].w = expf(v[kk].w - mx);
        s += v[kk].x + v[kk].y + v[kk].z + v[kk].w;
    }
    #pragma unroll
    for (int o = 16; o; o >>= 1) s += __shfl_xor_sync(0xffffffffu, s, o);
    float inv = 1.0f / s;
    #pragma unroll
    for (int kk = 0; kk < 8; kk++) {
        v[kk].x *= inv; v[kk].y *= inv; v[kk].z *= inv; v[kk].w *= inv;
        p[lane + 32 * kk] = v[kk];
    }
}

// ---------------- layernorm over last dim (block per row of 1024) ----------------
__global__ void ln_kernel(const float* __restrict__ X, const float* __restrict__ gw,
                          const float* __restrict__ bw, float* __restrict__ Y)
{
    __shared__ float red[8];
    __shared__ float stat[2];
    const int row = blockIdx.x;
    const int tid = threadIdx.x;
    const int lane = tid & 31, wid = tid >> 5;
    float4 x = ((const float4*)(X + (long long)row * 1024))[tid];

    float s = x.x + x.y + x.z + x.w;
    #pragma unroll
    for (int o = 16; o; o >>= 1) s += __shfl_xor_sync(0xffffffffu, s, o);
    if (lane == 0) red[wid] = s;
    __syncthreads();
    if (tid == 0) {
        float t = 0.f;
        for (int i = 0; i < 8; i++) t += red[i];
        stat[0] = t * (1.0f / 1024.0f);
    }
    __syncthreads();
    float mu = stat[0];
    float d0 = x.x - mu, d1 = x.y - mu, d2 = x.z - mu, d3 = x.w - mu;
    float sq = d0 * d0 + d1 * d1 + d2 * d2 + d3 * d3;
    #pragma unroll
    for (int o = 16; o; o >>= 1) sq += __shfl_xor_sync(0xffffffffu, sq, o);
    if (lane == 0) red[wid] = sq;
    __syncthreads();
    if (tid == 0) {
        float t = 0.f;
        for (int i = 0; i < 8; i++) t += red[i];
        stat[1] = rsqrtf(t * (1.0f / 1024.0f) + 1e-12f);
    }
    __syncthreads();
    float rs = stat[1];
    float4 g4 = ((const float4*)gw)[tid];
    float4 b4 = ((const float4*)bw)[tid];
    float4 y;
    y.x = d0 * rs * g4.x + b4.x;
    y.y = d1 * rs * g4.y + b4.y;
    y.z = d2 * rs * g4.z + b4.z;
    y.w = d3 * rs * g4.w + b4.w;
    ((float4*)(Y + (long long)row * 1024))[tid] = y;
}

// ---------------- orchestration ----------------
extern "C" void kernel_launch(void* const* d_in, const int* in_sizes, int n_in,
                              void* d_out, int out_size)
{
    (void)in_sizes; (void)n_in; (void)out_size;
    const float* h    = (const float*)d_in[0];
    const float* r    = (const float*)d_in[1];
    const float* msk  = (const float*)d_in[2];
    const float* segm = (const float*)d_in[3];
    const float* q_w  = (const float*)d_in[4];
    const float* k_w  = (const float*)d_in[5];
    const float* v_w  = (const float*)d_in[6];
    const float* o_w  = (const float*)d_in[7];
    const float* r_w  = (const float*)d_in[8];
    const float* rrb  = (const float*)d_in[9];
    const float* rsb  = (const float*)d_in[10];
    const float* rwb  = (const float*)d_in[11];
    const float* se   = (const float*)d_in[12];
    const float* ln1g = (const float*)d_in[13];
    const float* ln1b = (const float*)d_in[14];
    const float* w1   = (const float*)d_in[15];
    const float* b1   = (const float*)d_in[16];
    const float* w2   = (const float*)d_in[17];
    const float* b2   = (const float*)d_in[18];
    const float* ln2g = (const float*)d_in[19];
    const float* ln2b = (const float*)d_in[20];
    float* out = (float*)d_out;

    float *gq, *gk, *gv, *gkr, *gef, *gs, *gav, *gpre, *go1, *gffh, *gp2;
    cudaGetSymbolAddress((void**)&gq,  g_q);
    cudaGetSymbolAddress((void**)&gk,  g_k);
    cudaGetSymbolAddress((void**)&gv,  g_v);
    cudaGetSymbolAddress((void**)&gkr, g_kr);
    cudaGetSymbolAddress((void**)&gef, g_ef);
    cudaGetSymbolAddress((void**)&gs,  g_s);
    cudaGetSymbolAddress((void**)&gav, g_av);
    cudaGetSymbolAddress((void**)&gpre, g_pre);
    cudaGetSymbolAddress((void**)&go1, g_o1);
    cudaGetSymbolAddress((void**)&gffh, g_ffh);
    cudaGetSymbolAddress((void**)&gp2, g_p2);

    cudaFuncSetAttribute(score_kernel, cudaFuncAttributeMaxDynamicSharedMemorySize, SCORE_SMEM);

    // q/k/v projections: [4096,1024] @ [1024,1024]
    gemm_k<128,128,16,8,8,false,0><<<dim3(8,32,1),256>>>(h, q_w, gq, nullptr, nullptr,
        NTOK, DMODEL, DMODEL, 1024,1024,1024,0, 0,0,0,0,0,0, 0);
    gemm_k<128,128,16,8,8,false,0><<<dim3(8,32,1),256>>>(h, k_w, gk, nullptr, nullptr,
        NTOK, DMODEL, DMODEL, 1024,1024,1024,0, 0,0,0,0,0,0, 0);
    gemm_k<128,128,16,8,8,false,0><<<dim3(8,32,1),256>>>(h, v_w, gv, nullptr, nullptr,
        NTOK, DMODEL, DMODEL, 1024,1024,1024,0, 0,0,0,0,0,0, 0);
    // relative-position projection: [8192,1024] @ [1024,1024]
    gemm_k<128,128,16,8,8,false,0><<<dim3(8,64,1),256>>>(r, r_w, gkr, nullptr, nullptr,
        RTOK, DMODEL, DMODEL, 1024,1024,1024,0, 0,0,0,0,0,0, 0);

    ef_kernel<<<8192,256>>>(gq, rsb, se, gef);

    score_kernel<<<dim3(16,16,64),256,SCORE_SMEM>>>(gq, gk, gkr, rwb, rrb, gef, segm, msk, gs);
    softmax_kernel<<<8192,256>>>(gs);

    // attn_vec = P @ V, batched over (b,n), causal K-truncation
    gemm_k<64,64,16,4,4,false,0><<<dim3(1,16,64),256>>>(gs, gv, gav, nullptr, nullptr,
        1024, 64, 1024, 1024,4096,4096,0,
        16ll*1048576ll, 1048576ll, 1024ll, 64ll, 1024ll, 64ll, 1);

    // o-projection (B transposed: o_w is [h, n*d]) + residual h
    gemm_k<128,128,16,8,8,true,2><<<dim3(8,32,1),256>>>(gav, o_w, gpre, nullptr, h,
        NTOK, DMODEL, DMODEL, 1024,1024,1024,1024, 0,0,0,0,0,0, 0);
    ln_kernel<<<4096,256>>>(gpre, ln1g, ln1b, go1);

    // FF1 (+bias, exact GELU) and FF2 (+bias, +residual out1)
    gemm_k<128,128,16,8,8,false,1><<<dim3(32,32,1),256>>>(go1, w1, gffh, b1, nullptr,
        NTOK, DFF, DMODEL, 1024,4096,4096,0, 0,0,0,0,0,0, 0);
    gemm_k<128,128,16,8,8,false,3><<<dim3(8,32,1),256>>>(gffh, w2, gp2, b2, go1,
        NTOK, DMODEL, DFF, 4096,1024,1024,1024, 0,0,0,0,0,0, 0);
    ln_kernel<<<4096,256>>>(gp2, ln2g, ln2b, out);
}

// round 4
// speedup vs baseline: 2.0272x; 2.0272x over previous
#include <cuda_runtime.h>
#include <math.h>
#include <stdint.h>

// ---------------- problem constants ----------------
#define NTOK   4096      // QLEN*B
#define RTOK   8192      // RLEN*B
#define DMODEL 1024
#define NHEAD  16
#define DHEAD  64
#define DFF    4096

// ---------------- scratch (__device__ globals; allocation-free) ----------------
__device__ float g_q  [4096 * 1024];
__device__ float g_k  [4096 * 1024];
__device__ float g_v  [4096 * 1024];
__device__ float g_kr [8192 * 1024];
__device__ float g_ef [4096 * 16 * 2];
__device__ float g_s  [67108864];          // [64 (b,n)] x [1024 x 1024] scores->probs in place
__device__ float g_av [4096 * 1024];
__device__ float g_pre[4096 * 1024];
__device__ float g_o1 [4096 * 1024];
__device__ float g_ffh[4096 * 4096];
__device__ float g_p2 [4096 * 1024];

__device__ __forceinline__ float gelu_exact(float x) {
    return 0.5f * x * (1.0f + erff(x * 0.70710678118654752f));
}

__device__ __forceinline__ uint32_t f2tf32(float x) {
    uint32_t u;
    asm("cvt.rna.tf32.f32 %0, %1;" : "=r"(u) : "f"(x));
    return u;
}

__device__ __forceinline__ void mma_tf32(float* c, const uint32_t* a, const uint32_t* b) {
    asm volatile(
        "mma.sync.aligned.m16n8k8.row.col.f32.tf32.tf32.f32 "
        "{%0,%1,%2,%3}, {%4,%5,%6,%7}, {%8,%9}, {%0,%1,%2,%3};\n"
        : "+f"(c[0]), "+f"(c[1]), "+f"(c[2]), "+f"(c[3])
        : "r"(a[0]), "r"(a[1]), "r"(a[2]), "r"(a[3]), "r"(b[0]), "r"(b[1]));
}

// ---------------- tf32 tensor-core GEMM ----------------
// C[M,N] = A[M,K] @ B  (B row-major [K,N], or [N,K] if TRANSB). fp32 accumulate.
// batched over blockIdx.z (z = zb*16 + zn) with per-operand strides.
// EPI: 0 none, 1 bias+GELU(exact), 2 +residual, 3 bias+residual
// causal!=0: K-loop truncated at row0+BM.
// Smem k-major with stride BM+4 / BN+4 -> all fragment LDS.32 conflict-free.
template<int BM, int BN, int WGM, int WGN, bool TRANSB, int EPI>
__global__ __launch_bounds__(WGM * WGN * 32)
void gemm_tc(const float* __restrict__ A, const float* __restrict__ B,
             float* __restrict__ C, const float* __restrict__ bias,
             const float* __restrict__ R,
             int M, int N, int K, int lda, int ldb, int ldc, int ldr,
             long long sAb, long long sAn, long long sBb, long long sBn,
             long long sCb, long long sCn, int causal)
{
    constexpr int BK = 32;
    constexpr int THREADS = WGM * WGN * 32;
    constexpr int WTM = BM / WGM, WTN = BN / WGN;
    constexpr int MT = WTM / 16, NT = WTN / 8;
    constexpr int LDA_S = BM + 4, LDB_S = BN + 4;
    constexpr int NLA = BM * BK / (4 * THREADS);
    constexpr int NLB = BN * BK / (4 * THREADS);
    constexpr int BNQ = BN / 4;

    __shared__ float As[BK * LDA_S];
    __shared__ float Bs[BK * LDB_S];

    const int tid  = threadIdx.x;
    const int lane = tid & 31;
    const int warp = tid >> 5;
    const int wm = warp / WGN, wn = warp % WGN;

    const int zb = blockIdx.z >> 4, zn = blockIdx.z & 15;
    const float* Ap = A + zb * sAb + zn * sAn;
    const float* Bp = B + zb * sBb + zn * sBn;
    float*       Cp = C + zb * sCb + zn * sCn;

    const int row0 = blockIdx.y * BM;
    const int col0 = blockIdx.x * BN;
    const int kEnd = causal ? ((row0 + BM < K) ? (row0 + BM) : K) : K;

    float acc[MT][NT][4];
    #pragma unroll
    for (int mt = 0; mt < MT; mt++)
        #pragma unroll
        for (int nt = 0; nt < NT; nt++)
            #pragma unroll
            for (int q = 0; q < 4; q++) acc[mt][nt][q] = 0.0f;

    float4 stA[NLA], stB[NLB];

    auto loadA = [&](int kt) {
        #pragma unroll
        for (int it = 0; it < NLA; it++) {
            int idx = it * THREADS + tid;
            int rm = idx >> 3, kq = (idx & 7) * 4;
            stA[it] = *(const float4*)(Ap + (long long)(row0 + rm) * lda + kt + kq);
        }
    };
    auto loadB = [&](int kt) {
        if (!TRANSB) {
            #pragma unroll
            for (int it = 0; it < NLB; it++) {
                int idx = it * THREADS + tid;
                int kk = idx / BNQ, nq = (idx % BNQ) * 4;
                stB[it] = *(const float4*)(Bp + (long long)(kt + kk) * ldb + col0 + nq);
            }
        } else {
            #pragma unroll
            for (int it = 0; it < NLB; it++) {
                int idx = it * THREADS + tid;
                int nn = idx >> 3, kq = (idx & 7) * 4;
                stB[it] = *(const float4*)(Bp + (long long)(col0 + nn) * ldb + kt + kq);
            }
        }
    };

    loadA(0);
    loadB(0);

    for (int kt = 0; kt < kEnd; kt += BK) {
        // stage -> smem (convert to tf32)
        #pragma unroll
        for (int it = 0; it < NLA; it++) {
            int idx = it * THREADS + tid;
            int rm = idx >> 3, kq = (idx & 7) * 4;
            As[(kq + 0) * LDA_S + rm] = __uint_as_float(f2tf32(stA[it].x));
            As[(kq + 1) * LDA_S + rm] = __uint_as_float(f2tf32(stA[it].y));
            As[(kq + 2) * LDA_S + rm] = __uint_as_float(f2tf32(stA[it].z));
            As[(kq + 3) * LDA_S + rm] = __uint_as_float(f2tf32(stA[it].w));
        }
        if (!TRANSB) {
            #pragma unroll
            for (int it = 0; it < NLB; it++) {
                int idx = it * THREADS + tid;
                int kk = idx / BNQ, nq = (idx % BNQ) * 4;
                float4 v;
                v.x = __uint_as_float(f2tf32(stB[it].x));
                v.y = __uint_as_float(f2tf32(stB[it].y));
                v.z = __uint_as_float(f2tf32(stB[it].z));
                v.w = __uint_as_float(f2tf32(stB[it].w));
                *(float4*)&Bs[kk * LDB_S + nq] = v;
            }
        } else {
            #pragma unroll
            for (int it = 0; it < NLB; it++) {
                int idx = it * THREADS + tid;
                int nn = idx >> 3, kq = (idx & 7) * 4;
                Bs[(kq + 0) * LDB_S + nn] = __uint_as_float(f2tf32(stB[it].x));
                Bs[(kq + 1) * LDB_S + nn] = __uint_as_float(f2tf32(stB[it].y));
                Bs[(kq + 2) * LDB_S + nn] = __uint_as_float(f2tf32(stB[it].z));
                Bs[(kq + 3) * LDB_S + nn] = __uint_as_float(f2tf32(stB[it].w));
            }
        }
        __syncthreads();

        if (kt + BK < kEnd) { loadA(kt + BK); loadB(kt + BK); }

        #pragma unroll
        for (int ks = 0; ks < 4; ks++) {
            const int k0 = ks * 8;
            const int kc = k0 + (lane & 3);
            uint32_t aF[MT][4];
            const int ar = wm * WTM + (lane >> 2);
            #pragma unroll
            for (int mt = 0; mt < MT; mt++) {
                int r = ar + mt * 16;
                aF[mt][0] = __float_as_uint(As[kc * LDA_S + r]);
                aF[mt][1] = __float_as_uint(As[kc * LDA_S + r + 8]);
                aF[mt][2] = __float_as_uint(As[(kc + 4) * LDA_S + r]);
                aF[mt][3] = __float_as_uint(As[(kc + 4) * LDA_S + r + 8]);
            }
            uint32_t bF[NT][2];
            const int bn0 = wn * WTN + (lane >> 2);
            #pragma unroll
            for (int nt = 0; nt < NT; nt++) {
                int c = bn0 + nt * 8;
                bF[nt][0] = __float_as_uint(Bs[kc * LDB_S + c]);
                bF[nt][1] = __float_as_uint(Bs[(kc + 4) * LDB_S + c]);
            }
            #pragma unroll
            for (int mt = 0; mt < MT; mt++)
                #pragma unroll
                for (int nt = 0; nt < NT; nt++)
                    mma_tf32(acc[mt][nt], aF[mt], bF[nt]);
        }
        __syncthreads();
    }

    // epilogue
    #pragma unroll
    for (int mt = 0; mt < MT; mt++) {
        int rbase = row0 + wm * WTM + mt * 16 + (lane >> 2);
        #pragma unroll
        for (int nt = 0; nt < NT; nt++) {
            int c = col0 + wn * WTN + nt * 8 + (lane & 3) * 2;
            #pragma unroll
            for (int h2 = 0; h2 < 2; h2++) {
                int rr = rbase + h2 * 8;
                if (rr < M && c + 1 < N) {
                    float v0 = acc[mt][nt][h2 * 2];
                    float v1 = acc[mt][nt][h2 * 2 + 1];
                    if (EPI == 1) {
                        v0 = gelu_exact(v0 + bias[c]);
                        v1 = gelu_exact(v1 + bias[c + 1]);
                    }
                    if (EPI == 2) {
                        const float* rp = R + (long long)rr * ldr + c;
                        v0 += rp[0]; v1 += rp[1];
                    }
                    if (EPI == 3) {
                        const float* rp = R + (long long)rr * ldr + c;
                        v0 += bias[c] + rp[0]; v1 += bias[c + 1] + rp[1];
                    }
                    float2 o; o.x = v0; o.y = v1;
                    *(float2*)(Cp + (long long)rr * ldc + c) = o;
                }
            }
        }
    }
}

// ---------------- ef precompute ----------------
__global__ void ef_kernel(const float* __restrict__ q, const float* __restrict__ rsb,
                          const float* __restrict__ se, float* __restrict__ ef)
{
    const int pair = blockIdx.x * 8 + (threadIdx.x >> 5);
    const int lane = threadIdx.x & 31;
    const int t = pair >> 4, n = pair & 15;
    const float* qp = q + (long long)t * 1024 + n * 64;
    float e0 = 0.f, e1 = 0.f;
    #pragma unroll
    for (int d = lane; d < 64; d += 32) {
        float qv = qp[d] + rsb[n * 64 + d];
        e0 += qv * se[n * 64 + d];
        e1 += qv * se[1024 + n * 64 + d];
    }
    #pragma unroll
    for (int o = 16; o; o >>= 1) {
        e0 += __shfl_xor_sync(0xffffffffu, e0, o);
        e1 += __shfl_xor_sync(0xffffffffu, e1, o);
    }
    if (lane == 0) {
        ef[((long long)t * 16 + n) * 2]     = e0;
        ef[((long long)t * 16 + n) * 2 + 1] = e1;
    }
}

// ---------------- fused score kernel ----------------
static const int SCORE_SMEM = (64 * 68 * 2 + 64 * 132 + 64 * 3) * 4;  // 69376 B

__global__ __launch_bounds__(256)
void score_kernel(const float* __restrict__ q, const float* __restrict__ k,
                  const float* __restrict__ kr,
                  const float* __restrict__ rwb, const float* __restrict__ rrb,
                  const float* __restrict__ ef, const float* __restrict__ segm,
                  const float* __restrict__ msk, float* __restrict__ S)
{
    const int j0 = blockIdx.x * 64, i0 = blockIdx.y * 64;
    if (j0 > i0) return;  // fully-masked tile: never written, never read downstream

    const int z = blockIdx.z, b = z >> 4, n = z & 15;
    const long long sbase = (long long)z * 1048576ll;
    const int tid = threadIdx.x;

    extern __shared__ float sm[];
    float* Qt   = sm;
    float* Kt   = Qt + 64 * 68;
    float* Krt  = Kt + 64 * 68;
    float* dbs  = Krt + 64 * 132;
    float* efs0 = dbs + 64;
    float* efs1 = efs0 + 64;

    const float* qb  = q  + b * 1024 + n * 64;
    const float* kb  = k  + b * 1024 + n * 64;
    const float* krb = kr + b * 1024 + n * 64;

    for (int e = tid; e < 4096; e += 256) {
        int row = e >> 6, d = e & 63;
        Qt[d * 68 + row] = qb[(long long)(i0 + row) * 4096 + d] + rwb[n * 64 + d];
        Kt[d * 68 + row] = kb[(long long)(j0 + row) * 4096 + d];
    }
    const int rel0 = j0 - i0 + 1024 - 63;
    for (int e = tid; e < 127 * 64; e += 256) {
        int row = e >> 6, d = e & 63;
        Krt[d * 132 + row] = krb[(long long)(rel0 + row) * 4096 + d];
    }
    if (tid < 64) {
        dbs[tid] = rrb[n * 64 + tid] - rwb[n * 64 + tid];
        int t = (i0 + tid) * 4 + b;
        efs0[tid] = ef[((long long)t * 16 + n) * 2];
        efs1[tid] = ef[((long long)t * 16 + n) * 2 + 1];
    }
    __syncthreads();

    const int tx = tid & 15, ty = tid >> 4;
    const int ib = ty * 4, jb = tx * 4;
    const int r0 = jb - ib + 60;

    float ac[4][4] = {}, bd[4][4] = {};
    #pragma unroll 4
    for (int kk = 0; kk < 64; kk++) {
        float db = dbs[kk];
        float qa[4], kv[4], krv[7];
        #pragma unroll
        for (int a = 0; a < 4; a++) qa[a] = Qt[kk * 68 + ib + a];
        #pragma unroll
        for (int c = 0; c < 4; c++) kv[c] = Kt[kk * 68 + jb + c];
        #pragma unroll
        for (int m = 0; m < 7; m++) krv[m] = Krt[kk * 132 + r0 + m];
        #pragma unroll
        for (int a = 0; a < 4; a++) {
            float qd = qa[a] + db;
            #pragma unroll
            for (int c = 0; c < 4; c++) {
                ac[a][c] += qa[a] * kv[c];
                bd[a][c] += qd * krv[c - a + 3];
            }
        }
    }

    #pragma unroll
    for (int a = 0; a < 4; a++) {
        int i = i0 + ib + a;
        float e0 = efs0[ib + a], e1 = efs1[ib + a];
        #pragma unroll
        for (int c = 0; c < 4; c++) {
            int j = j0 + jb + c;
            long long mi = ((long long)i * 1024 + j) * 4 + b;
            float seg1 = segm[mi * 2 + 1];
            float mv   = msk[mi];
            S[sbase + (long long)i * 1024 + j] =
                (ac[a][c] + bd[a][c] + e0 + seg1 * (e1 - e0)) * 0.125f - 1e30f * mv;
        }
    }
}

// ---------------- causal-length-aware in-place softmax (warp per row) ----------------
__global__ void softmax_kernel(float* __restrict__ S)
{
    const int row  = blockIdx.x * 8 + (threadIdx.x >> 5);
    const int lane = threadIdx.x & 31;
    const int i    = row & 1023;
    const int P64  = ((i >> 6) + 1) << 6;           // valid (written) width, 64-aligned
    float4* p = (float4*)(S + (long long)row * 1024);
    float4 v[8];
    float mx = -3.4e38f;
    #pragma unroll
    for (int kk = 0; kk < 8; kk++) {
        int j4 = (lane + 32 * kk) * 4;
        if (j4 < P64) v[kk] = p[lane + 32 * kk];
        else          v[kk] = make_float4(-1e30f, -1e30f, -1e30f, -1e30f);
        mx = fmaxf(mx, fmaxf(fmaxf(v[kk].x, v[kk].y), fmaxf(v[kk].z, v[kk].w)));
    }
    #pragma unroll
    for (int o = 16; o; o >>= 1) mx = fmaxf(mx, __shfl_xor_sync(0xffffffffu, mx, o));
    float s = 0.f;
    #pragma unroll
    for (int kk = 0; kk < 8; kk++) {
        v[kk].x = expf(v[kk].x - mx); v[kk].y = expf(v[kk].y - mx);
        v[kk].z = expf(v[kk].z - mx); v[kk].w = expf(v[kk].w - mx);
        s += v[kk].x + v[kk].y + v[kk].z + v[kk].w;
    }
    #pragma unroll
    for (int o = 16; o; o >>= 1) s += __shfl_xor_sync(0xffffffffu, s, o);
    float inv = 1.0f / s;
    #pragma unroll
    for (int kk = 0; kk < 8; kk++) {
        int j4 = (lane + 32 * kk) * 4;
        if (j4 < P64) {
            v[kk].x *= inv; v[kk].y *= inv; v[kk].z *= inv; v[kk].w *= inv;
            p[lane + 32 * kk] = v[kk];
        }
    }
}

// ---------------- layernorm ----------------
__global__ void ln_kernel(const float* __restrict__ X, const float* __restrict__ gw,
                          const float* __restrict__ bw, float* __restrict__ Y)
{
    __shared__ float red[8];
    __shared__ float stat[2];
    const int row = blockIdx.x;
    const int tid = threadIdx.x;
    const int lane = tid & 31, wid = tid >> 5;
    float4 x = ((const float4*)(X + (long long)row * 1024))[tid];

    float s = x.x + x.y + x.z + x.w;
    #pragma unroll
    for (int o = 16; o; o >>= 1) s += __shfl_xor_sync(0xffffffffu, s, o);
    if (lane == 0) red[wid] = s;
    __syncthreads();
    if (tid == 0) {
        float t = 0.f;
        for (int i = 0; i < 8; i++) t += red[i];
        stat[0] = t * (1.0f / 1024.0f);
    }
    __syncthreads();
    float mu = stat[0];
    float d0 = x.x - mu, d1 = x.y - mu, d2 = x.z - mu, d3 = x.w - mu;
    float sq = d0 * d0 + d1 * d1 + d2 * d2 + d3 * d3;
    #pragma unroll
    for (int o = 16; o; o >>= 1) sq += __shfl_xor_sync(0xffffffffu, sq, o);
    if (lane == 0) red[wid] = sq;
    __syncthreads();
    if (tid == 0) {
        float t = 0.f;
        for (int i = 0; i < 8; i++) t += red[i];
        stat[1] = rsqrtf(t * (1.0f / 1024.0f) + 1e-12f);
    }
    __syncthreads();
    float rs = stat[1];
    float4 g4 = ((const float4*)gw)[tid];
    float4 b4 = ((const float4*)bw)[tid];
    float4 y;
    y.x = d0 * rs * g4.x + b4.x;
    y.y = d1 * rs * g4.y + b4.y;
    y.z = d2 * rs * g4.z + b4.z;
    y.w = d3 * rs * g4.w + b4.w;
    ((float4*)(Y + (long long)row * 1024))[tid] = y;
}

// ---------------- orchestration ----------------
extern "C" void kernel_launch(void* const* d_in, const int* in_sizes, int n_in,
                              void* d_out, int out_size)
{
    (void)in_sizes; (void)n_in; (void)out_size;
    const float* h    = (const float*)d_in[0];
    const float* r    = (const float*)d_in[1];
    const float* msk  = (const float*)d_in[2];
    const float* segm = (const float*)d_in[3];
    const float* q_w  = (const float*)d_in[4];
    const float* k_w  = (const float*)d_in[5];
    const float* v_w  = (const float*)d_in[6];
    const float* o_w  = (const float*)d_in[7];
    const float* r_w  = (const float*)d_in[8];
    const float* rrb  = (const float*)d_in[9];
    const float* rsb  = (const float*)d_in[10];
    const float* rwb  = (const float*)d_in[11];
    const float* se   = (const float*)d_in[12];
    const float* ln1g = (const float*)d_in[13];
    const float* ln1b = (const float*)d_in[14];
    const float* w1   = (const float*)d_in[15];
    const float* b1   = (const float*)d_in[16];
    const float* w2   = (const float*)d_in[17];
    const float* b2   = (const float*)d_in[18];
    const float* ln2g = (const float*)d_in[19];
    const float* ln2b = (const float*)d_in[20];
    float* out = (float*)d_out;

    float *gq, *gk, *gv, *gkr, *gef, *gs, *gav, *gpre, *go1, *gffh, *gp2;
    cudaGetSymbolAddress((void**)&gq,  g_q);
    cudaGetSymbolAddress((void**)&gk,  g_k);
    cudaGetSymbolAddress((void**)&gv,  g_v);
    cudaGetSymbolAddress((void**)&gkr, g_kr);
    cudaGetSymbolAddress((void**)&gef, g_ef);
    cudaGetSymbolAddress((void**)&gs,  g_s);
    cudaGetSymbolAddress((void**)&gav, g_av);
    cudaGetSymbolAddress((void**)&gpre, g_pre);
    cudaGetSymbolAddress((void**)&go1, g_o1);
    cudaGetSymbolAddress((void**)&gffh, g_ffh);
    cudaGetSymbolAddress((void**)&gp2, g_p2);

    cudaFuncSetAttribute(score_kernel, cudaFuncAttributeMaxDynamicSharedMemorySize, SCORE_SMEM);

    // q/k/v projections (tf32 tensor cores)
    gemm_tc<128,128,4,2,false,0><<<dim3(8,32,1),256>>>(h, q_w, gq, nullptr, nullptr,
        NTOK, DMODEL, DMODEL, 1024,1024,1024,0, 0,0,0,0,0,0, 0);
    gemm_tc<128,128,4,2,false,0><<<dim3(8,32,1),256>>>(h, k_w, gk, nullptr, nullptr,
        NTOK, DMODEL, DMODEL, 1024,1024,1024,0, 0,0,0,0,0,0, 0);
    gemm_tc<128,128,4,2,false,0><<<dim3(8,32,1),256>>>(h, v_w, gv, nullptr, nullptr,
        NTOK, DMODEL, DMODEL, 1024,1024,1024,0, 0,0,0,0,0,0, 0);
    // relative projection: only rel rows <= 1087 are read -> rows [0, 4352) = 34 blocks
    gemm_tc<128,128,4,2,false,0><<<dim3(8,34,1),256>>>(r, r_w, gkr, nullptr, nullptr,
        RTOK, DMODEL, DMODEL, 1024,1024,1024,0, 0,0,0,0,0,0, 0);

    ef_kernel<<<8192,256>>>(gq, rsb, se, gef);

    score_kernel<<<dim3(16,16,64),256,SCORE_SMEM>>>(gq, gk, gkr, rwb, rrb, gef, segm, msk, gs);
    softmax_kernel<<<8192,256>>>(gs);

    // attn_vec = P @ V, batched over (b,n), causal K-truncation (tf32)
    gemm_tc<64,64,4,2,false,0><<<dim3(1,16,64),256>>>(gs, gv, gav, nullptr, nullptr,
        1024, 64, 1024, 1024,4096,4096,0,
        16ll*1048576ll, 1048576ll, 1024ll, 64ll, 1024ll, 64ll, 1);

    // o-projection (B transposed) + residual h
    gemm_tc<128,128,4,2,true,2><<<dim3(8,32,1),256>>>(gav, o_w, gpre, nullptr, h,
        NTOK, DMODEL, DMODEL, 1024,1024,1024,1024, 0,0,0,0,0,0, 0);
    ln_kernel<<<4096,256>>>(gpre, ln1g, ln1b, go1);

    // FF1 (+bias, exact GELU) and FF2 (+bias, +residual out1)
    gemm_tc<128,128,4,2,false,1><<<dim3(32,32,1),256>>>(go1, w1, gffh, b1, nullptr,
        NTOK, DFF, DMODEL, 1024,4096,4096,0, 0,0,0,0,0,0, 0);
    gemm_tc<128,128,4,2,false,3><<<dim3(8,32,1),256>>>(gffh, w2, gp2, b2, go1,
        NTOK, DMODEL, DFF, 4096,1024,1024,1024, 0,0,0,0,0,0, 0);
    ln_kernel<<<4096,256>>>(gp2, ln2g, ln2b, out);
}

// round 5
// speedup vs baseline: 2.5349x; 1.2504x over previous
#include <cuda_runtime.h>
#include <math.h>
#include <stdint.h>

// ---------------- problem constants ----------------
#define NTOK   4096      // QLEN*B
#define RTOK   8192      // RLEN*B
#define DMODEL 1024
#define NHEAD  16
#define DHEAD  64
#define DFF    4096

// ---------------- scratch (__device__ globals; allocation-free) ----------------
__device__ float g_q  [4096 * 1024];
__device__ float g_k  [4096 * 1024];
__device__ float g_v  [4096 * 1024];
__device__ float g_kr [8192 * 1024];
__device__ float g_ef [4096 * 16 * 2];
__device__ float g_s  [67108864];          // [64 (b,n)] x [1024 x 1024] scores->probs in place
__device__ float g_av [4096 * 1024];
__device__ float g_pre[4096 * 1024];
__device__ float g_o1 [4096 * 1024];
__device__ float g_ffh[4096 * 4096];
__device__ float g_p2 [4096 * 1024];

__device__ __forceinline__ float gelu_exact(float x) {
    return 0.5f * x * (1.0f + erff(x * 0.70710678118654752f));
}

__device__ __forceinline__ uint32_t f2tf32(float x) {
    uint32_t u;
    asm("cvt.rna.tf32.f32 %0, %1;" : "=r"(u) : "f"(x));
    return u;
}

__device__ __forceinline__ void mma_tf32(float* c, const uint32_t* a, const uint32_t* b) {
    asm volatile(
        "mma.sync.aligned.m16n8k8.row.col.f32.tf32.tf32.f32 "
        "{%0,%1,%2,%3}, {%4,%5,%6,%7}, {%8,%9}, {%0,%1,%2,%3};\n"
        : "+f"(c[0]), "+f"(c[1]), "+f"(c[2]), "+f"(c[3])
        : "r"(a[0]), "r"(a[1]), "r"(a[2]), "r"(a[3]), "r"(b[0]), "r"(b[1]));
}

__device__ __forceinline__ void cp_async16(float* s, const float* g) {
    uint32_t sa = (uint32_t)__cvta_generic_to_shared(s);
    asm volatile("cp.async.cg.shared.global [%0], [%1], 16;" :: "r"(sa), "l"(g));
}
__device__ __forceinline__ void cp_commit() { asm volatile("cp.async.commit_group;"); }
template<int N> __device__ __forceinline__ void cp_wait() {
    asm volatile("cp.async.wait_group %0;" :: "n"(N));
}

// ---------------- tf32 tensor-core GEMM, cp.async double-buffered ----------------
// C[M,N] = A[M,K] @ B  (B row-major [K,N], or [N,K] if TRANSB). fp32 accumulate.
// batched over blockIdx.z (z = zb*16 + zn) with per-operand strides.
// EPI: 0 none, 1 bias+GELU(exact), 2 +residual, 3 bias+residual
// causal!=0: K-loop truncated at row0+BM.
// Smem: A m-major [BM][BK+4], B [BK][BN+4] (or [BN][BK+4] if TRANSB);
// strides ≡ 4 mod 32 -> all fragment LDS.32 conflict-free; cp.async 16B contiguous.
template<int BM, int BN, int WGM, int WGN, bool TRANSB, int EPI>
__global__ __launch_bounds__(WGM * WGN * 32, 2)
void gemm_tc(const float* __restrict__ A, const float* __restrict__ B,
             float* __restrict__ C, const float* __restrict__ bias,
             const float* __restrict__ R,
             int M, int N, int K, int lda, int ldb, int ldc, int ldr,
             long long sAb, long long sAn, long long sBb, long long sBn,
             long long sCb, long long sCn, int causal)
{
    constexpr int BK = 32;
    constexpr int THREADS = WGM * WGN * 32;
    constexpr int WTM = BM / WGM, WTN = BN / WGN;
    constexpr int MT = WTM / 16, NT = WTN / 8;
    constexpr int LDA_S = BK + 4;                      // 36
    constexpr int ASZ = BM * LDA_S;
    constexpr int BSZ = TRANSB ? BN * (BK + 4) : BK * (BN + 4);
    constexpr int NLA = BM * BK / (4 * THREADS);
    constexpr int NLB = BN * BK / (4 * THREADS);
    constexpr int BNQ = BN / 4;

    extern __shared__ float sm[];
    float* Abase = sm;
    float* Bbase = sm + 2 * ASZ;

    const int tid  = threadIdx.x;
    const int lane = tid & 31;
    const int warp = tid >> 5;
    const int wm = warp / WGN, wn = warp % WGN;

    const int zb = blockIdx.z >> 4, zn = blockIdx.z & 15;
    const float* Ap = A + zb * sAb + zn * sAn;
    const float* Bp = B + zb * sBb + zn * sBn;
    float*       Cp = C + zb * sCb + zn * sCn;

    const int row0 = blockIdx.y * BM;
    const int col0 = blockIdx.x * BN;
    const int kEnd = causal ? ((row0 + BM < K) ? (row0 + BM) : K) : K;

    float acc[MT][NT][4];
    #pragma unroll
    for (int mt = 0; mt < MT; mt++)
        #pragma unroll
        for (int nt = 0; nt < NT; nt++)
            #pragma unroll
            for (int q = 0; q < 4; q++) acc[mt][nt][q] = 0.0f;

    auto loadAB = [&](int kt, int stage) {
        float* As = Abase + stage * ASZ;
        #pragma unroll
        for (int it = 0; it < NLA; it++) {
            int idx = it * THREADS + tid;
            int rm = idx >> 3, kq = (idx & 7) << 2;
            cp_async16(As + rm * LDA_S + kq,
                       Ap + (long long)(row0 + rm) * lda + kt + kq);
        }
        float* Bs = Bbase + stage * BSZ;
        if (!TRANSB) {
            #pragma unroll
            for (int it = 0; it < NLB; it++) {
                int idx = it * THREADS + tid;
                int kk = idx / BNQ, nq = (idx % BNQ) << 2;
                cp_async16(Bs + kk * (BN + 4) + nq,
                           Bp + (long long)(kt + kk) * ldb + col0 + nq);
            }
        } else {
            #pragma unroll
            for (int it = 0; it < NLB; it++) {
                int idx = it * THREADS + tid;
                int nn = idx >> 3, kq = (idx & 7) << 2;
                cp_async16(Bs + nn * (BK + 4) + kq,
                           Bp + (long long)(col0 + nn) * ldb + kt + kq);
            }
        }
        cp_commit();
    };

    const int ntile = kEnd / BK;
    loadAB(0, 0);

    for (int i = 0; i < ntile; i++) {
        if (i + 1 < ntile) { loadAB((i + 1) * BK, (i + 1) & 1); cp_wait<1>(); }
        else               { cp_wait<0>(); }
        __syncthreads();

        const float* As = Abase + (i & 1) * ASZ;
        const float* Bs = Bbase + (i & 1) * BSZ;

        #pragma unroll
        for (int ks = 0; ks < 4; ks++) {
            const int kc = ks * 8 + (lane & 3);
            uint32_t aF[MT][4];
            const int ar = wm * WTM + (lane >> 2);
            #pragma unroll
            for (int mt = 0; mt < MT; mt++) {
                const float* ap = As + (ar + mt * 16) * LDA_S;
                aF[mt][0] = f2tf32(ap[kc]);
                aF[mt][1] = f2tf32(ap[8 * LDA_S + kc]);
                aF[mt][2] = f2tf32(ap[kc + 4]);
                aF[mt][3] = f2tf32(ap[8 * LDA_S + kc + 4]);
            }
            uint32_t bF[NT][2];
            const int c0 = wn * WTN + (lane >> 2);
            if (!TRANSB) {
                #pragma unroll
                for (int nt = 0; nt < NT; nt++) {
                    bF[nt][0] = f2tf32(Bs[kc * (BN + 4) + c0 + nt * 8]);
                    bF[nt][1] = f2tf32(Bs[(kc + 4) * (BN + 4) + c0 + nt * 8]);
                }
            } else {
                #pragma unroll
                for (int nt = 0; nt < NT; nt++) {
                    const float* bp = Bs + (c0 + nt * 8) * (BK + 4);
                    bF[nt][0] = f2tf32(bp[kc]);
                    bF[nt][1] = f2tf32(bp[kc + 4]);
                }
            }
            #pragma unroll
            for (int mt = 0; mt < MT; mt++)
                #pragma unroll
                for (int nt = 0; nt < NT; nt++)
                    mma_tf32(acc[mt][nt], aF[mt], bF[nt]);
        }
        __syncthreads();
    }

    // epilogue
    #pragma unroll
    for (int mt = 0; mt < MT; mt++) {
        int rbase = row0 + wm * WTM + mt * 16 + (lane >> 2);
        #pragma unroll
        for (int nt = 0; nt < NT; nt++) {
            int c = col0 + wn * WTN + nt * 8 + (lane & 3) * 2;
            #pragma unroll
            for (int h2 = 0; h2 < 2; h2++) {
                int rr = rbase + h2 * 8;
                if (rr < M && c + 1 < N) {
                    float v0 = acc[mt][nt][h2 * 2];
                    float v1 = acc[mt][nt][h2 * 2 + 1];
                    if (EPI == 1) {
                        v0 = gelu_exact(v0 + bias[c]);
                        v1 = gelu_exact(v1 + bias[c + 1]);
                    }
                    if (EPI == 2) {
                        const float* rp = R + (long long)rr * ldr + c;
                        v0 += rp[0]; v1 += rp[1];
                    }
                    if (EPI == 3) {
                        const float* rp = R + (long long)rr * ldr + c;
                        v0 += bias[c] + rp[0]; v1 += bias[c + 1] + rp[1];
                    }
                    float2 o; o.x = v0; o.y = v1;
                    *(float2*)(Cp + (long long)rr * ldc + c) = o;
                }
            }
        }
    }
}

constexpr int gemm_smem(int BM, int BN, bool TRANSB) {
    return (2 * BM * 36 + 2 * (TRANSB ? BN * 36 : 32 * (BN + 4))) * 4;
}

// ---------------- ef precompute ----------------
__global__ void ef_kernel(const float* __restrict__ q, const float* __restrict__ rsb,
                          const float* __restrict__ se, float* __restrict__ ef)
{
    const int pair = blockIdx.x * 8 + (threadIdx.x >> 5);
    const int lane = threadIdx.x & 31;
    const int t = pair >> 4, n = pair & 15;
    const float* qp = q + (long long)t * 1024 + n * 64;
    float e0 = 0.f, e1 = 0.f;
    #pragma unroll
    for (int d = lane; d < 64; d += 32) {
        float qv = qp[d] + rsb[n * 64 + d];
        e0 += qv * se[n * 64 + d];
        e1 += qv * se[1024 + n * 64 + d];
    }
    #pragma unroll
    for (int o = 16; o; o >>= 1) {
        e0 += __shfl_xor_sync(0xffffffffu, e0, o);
        e1 += __shfl_xor_sync(0xffffffffu, e1, o);
    }
    if (lane == 0) {
        ef[((long long)t * 16 + n) * 2]     = e0;
        ef[((long long)t * 16 + n) * 2 + 1] = e1;
    }
}

// ---------------- fused score kernel ----------------
static const int SCORE_SMEM = (64 * 68 * 2 + 64 * 132 + 64 * 3) * 4;  // 69376 B

__global__ __launch_bounds__(256)
void score_kernel(const float* __restrict__ q, const float* __restrict__ k,
                  const float* __restrict__ kr,
                  const float* __restrict__ rwb, const float* __restrict__ rrb,
                  const float* __restrict__ ef, const float* __restrict__ segm,
                  const float* __restrict__ msk, float* __restrict__ S)
{
    const int j0 = blockIdx.x * 64, i0 = blockIdx.y * 64;
    if (j0 > i0) return;  // fully-masked tile: never written, never read downstream

    const int z = blockIdx.z, b = z >> 4, n = z & 15;
    const long long sbase = (long long)z * 1048576ll;
    const int tid = threadIdx.x;

    extern __shared__ float sm[];
    float* Qt   = sm;
    float* Kt   = Qt + 64 * 68;
    float* Krt  = Kt + 64 * 68;
    float* dbs  = Krt + 64 * 132;
    float* efs0 = dbs + 64;
    float* efs1 = efs0 + 64;

    const float* qb  = q  + b * 1024 + n * 64;
    const float* kb  = k  + b * 1024 + n * 64;
    const float* krb = kr + b * 1024 + n * 64;

    for (int e = tid; e < 4096; e += 256) {
        int row = e >> 6, d = e & 63;
        Qt[d * 68 + row] = qb[(long long)(i0 + row) * 4096 + d] + rwb[n * 64 + d];
        Kt[d * 68 + row] = kb[(long long)(j0 + row) * 4096 + d];
    }
    const int rel0 = j0 - i0 + 1024 - 63;
    for (int e = tid; e < 127 * 64; e += 256) {
        int row = e >> 6, d = e & 63;
        Krt[d * 132 + row] = krb[(long long)(rel0 + row) * 4096 + d];
    }
    if (tid < 64) {
        dbs[tid] = rrb[n * 64 + tid] - rwb[n * 64 + tid];
        int t = (i0 + tid) * 4 + b;
        efs0[tid] = ef[((long long)t * 16 + n) * 2];
        efs1[tid] = ef[((long long)t * 16 + n) * 2 + 1];
    }
    __syncthreads();

    const int tx = tid & 15, ty = tid >> 4;
    const int ib = ty * 4, jb = tx * 4;
    const int r0 = jb - ib + 60;

    float ac[4][4] = {}, bd[4][4] = {};
    #pragma unroll 4
    for (int kk = 0; kk < 64; kk++) {
        float db = dbs[kk];
        float qa[4], kv[4], krv[7];
        #pragma unroll
        for (int a = 0; a < 4; a++) qa[a] = Qt[kk * 68 + ib + a];
        #pragma unroll
        for (int c = 0; c < 4; c++) kv[c] = Kt[kk * 68 + jb + c];
        #pragma unroll
        for (int m = 0; m < 7; m++) krv[m] = Krt[kk * 132 + r0 + m];
        #pragma unroll
        for (int a = 0; a < 4; a++) {
            float qd = qa[a] + db;
            #pragma unroll
            for (int c = 0; c < 4; c++) {
                ac[a][c] += qa[a] * kv[c];
                bd[a][c] += qd * krv[c - a + 3];
            }
        }
    }

    #pragma unroll
    for (int a = 0; a < 4; a++) {
        int i = i0 + ib + a;
        float e0 = efs0[ib + a], e1 = efs1[ib + a];
        #pragma unroll
        for (int c = 0; c < 4; c++) {
            int j = j0 + jb + c;
            long long mi = ((long long)i * 1024 + j) * 4 + b;
            float seg1 = segm[mi * 2 + 1];
            float mv   = msk[mi];
            S[sbase + (long long)i * 1024 + j] =
                (ac[a][c] + bd[a][c] + e0 + seg1 * (e1 - e0)) * 0.125f - 1e30f * mv;
        }
    }
}

// ---------------- causal-length-aware in-place softmax (warp per row) ----------------
__global__ void softmax_kernel(float* __restrict__ S)
{
    const int row  = blockIdx.x * 8 + (threadIdx.x >> 5);
    const int lane = threadIdx.x & 31;
    const int i    = row & 1023;
    const int P64  = ((i >> 6) + 1) << 6;           // valid (written) width, 64-aligned
    float4* p = (float4*)(S + (long long)row * 1024);
    float4 v[8];
    float mx = -3.4e38f;
    #pragma unroll
    for (int kk = 0; kk < 8; kk++) {
        int j4 = (lane + 32 * kk) * 4;
        if (j4 < P64) v[kk] = p[lane + 32 * kk];
        else          v[kk] = make_float4(-1e30f, -1e30f, -1e30f, -1e30f);
        mx = fmaxf(mx, fmaxf(fmaxf(v[kk].x, v[kk].y), fmaxf(v[kk].z, v[kk].w)));
    }
    #pragma unroll
    for (int o = 16; o; o >>= 1) mx = fmaxf(mx, __shfl_xor_sync(0xffffffffu, mx, o));
    float s = 0.f;
    #pragma unroll
    for (int kk = 0; kk < 8; kk++) {
        v[kk].x = expf(v[kk].x - mx); v[kk].y = expf(v[kk].y - mx);
        v[kk].z = expf(v[kk].z - mx); v[kk].w = expf(v[kk].w - mx);
        s += v[kk].x + v[kk].y + v[kk].z + v[kk].w;
    }
    #pragma unroll
    for (int o = 16; o; o >>= 1) s += __shfl_xor_sync(0xffffffffu, s, o);
    float inv = 1.0f / s;
    #pragma unroll
    for (int kk = 0; kk < 8; kk++) {
        int j4 = (lane + 32 * kk) * 4;
        if (j4 < P64) {
            v[kk].x *= inv; v[kk].y *= inv; v[kk].z *= inv; v[kk].w *= inv;
            p[lane + 32 * kk] = v[kk];
        }
    }
}

// ---------------- layernorm ----------------
__global__ void ln_kernel(const float* __restrict__ X, const float* __restrict__ gw,
                          const float* __restrict__ bw, float* __restrict__ Y)
{
    __shared__ float red[8];
    __shared__ float stat[2];
    const int row = blockIdx.x;
    const int tid = threadIdx.x;
    const int lane = tid & 31, wid = tid >> 5;
    float4 x = ((const float4*)(X + (long long)row * 1024))[tid];

    float s = x.x + x.y + x.z + x.w;
    #pragma unroll
    for (int o = 16; o; o >>= 1) s += __shfl_xor_sync(0xffffffffu, s, o);
    if (lane == 0) red[wid] = s;
    __syncthreads();
    if (tid == 0) {
        float t = 0.f;
        for (int i = 0; i < 8; i++) t += red[i];
        stat[0] = t * (1.0f / 1024.0f);
    }
    __syncthreads();
    float mu = stat[0];
    float d0 = x.x - mu, d1 = x.y - mu, d2 = x.z - mu, d3 = x.w - mu;
    float sq = d0 * d0 + d1 * d1 + d2 * d2 + d3 * d3;
    #pragma unroll
    for (int o = 16; o; o >>= 1) sq += __shfl_xor_sync(0xffffffffu, sq, o);
    if (lane == 0) red[wid] = sq;
    __syncthreads();
    if (tid == 0) {
        float t = 0.f;
        for (int i = 0; i < 8; i++) t += red[i];
        stat[1] = rsqrtf(t * (1.0f / 1024.0f) + 1e-12f);
    }
    __syncthreads();
    float rs = stat[1];
    float4 g4 = ((const float4*)gw)[tid];
    float4 b4 = ((const float4*)bw)[tid];
    float4 y;
    y.x = d0 * rs * g4.x + b4.x;
    y.y = d1 * rs * g4.y + b4.y;
    y.z = d2 * rs * g4.z + b4.z;
    y.w = d3 * rs * g4.w + b4.w;
    ((float4*)(Y + (long long)row * 1024))[tid] = y;
}

// ---------------- orchestration ----------------
extern "C" void kernel_launch(void* const* d_in, const int* in_sizes, int n_in,
                              void* d_out, int out_size)
{
    (void)in_sizes; (void)n_in; (void)out_size;
    const float* h    = (const float*)d_in[0];
    const float* r    = (const float*)d_in[1];
    const float* msk  = (const float*)d_in[2];
    const float* segm = (const float*)d_in[3];
    const float* q_w  = (const float*)d_in[4];
    const float* k_w  = (const float*)d_in[5];
    const float* v_w  = (const float*)d_in[6];
    const float* o_w  = (const float*)d_in[7];
    const float* r_w  = (const float*)d_in[8];
    const float* rrb  = (const float*)d_in[9];
    const float* rsb  = (const float*)d_in[10];
    const float* rwb  = (const float*)d_in[11];
    const float* se   = (const float*)d_in[12];
    const float* ln1g = (const float*)d_in[13];
    const float* ln1b = (const float*)d_in[14];
    const float* w1   = (const float*)d_in[15];
    const float* b1   = (const float*)d_in[16];
    const float* w2   = (const float*)d_in[17];
    const float* b2   = (const float*)d_in[18];
    const float* ln2g = (const float*)d_in[19];
    const float* ln2b = (const float*)d_in[20];
    float* out = (float*)d_out;

    float *gq, *gk, *gv, *gkr, *gef, *gs, *gav, *gpre, *go1, *gffh, *gp2;
    cudaGetSymbolAddress((void**)&gq,  g_q);
    cudaGetSymbolAddress((void**)&gk,  g_k);
    cudaGetSymbolAddress((void**)&gv,  g_v);
    cudaGetSymbolAddress((void**)&gkr, g_kr);
    cudaGetSymbolAddress((void**)&gef, g_ef);
    cudaGetSymbolAddress((void**)&gs,  g_s);
    cudaGetSymbolAddress((void**)&gav, g_av);
    cudaGetSymbolAddress((void**)&gpre, g_pre);
    cudaGetSymbolAddress((void**)&go1, g_o1);
    cudaGetSymbolAddress((void**)&gffh, g_ffh);
    cudaGetSymbolAddress((void**)&gp2, g_p2);

    const int SM_NRM = gemm_smem(128, 128, false);   // 70656
    const int SM_TRB = gemm_smem(128, 128, true);    // 73728
    const int SM_PV  = gemm_smem(64, 64, false);     // 35840

    cudaFuncSetAttribute(score_kernel, cudaFuncAttributeMaxDynamicSharedMemorySize, SCORE_SMEM);
    cudaFuncSetAttribute((const void*)gemm_tc<128,128,4,2,false,0>,
                         cudaFuncAttributeMaxDynamicSharedMemorySize, SM_NRM);
    cudaFuncSetAttribute((const void*)gemm_tc<128,128,4,2,true,2>,
                         cudaFuncAttributeMaxDynamicSharedMemorySize, SM_TRB);
    cudaFuncSetAttribute((const void*)gemm_tc<128,128,4,2,false,1>,
                         cudaFuncAttributeMaxDynamicSharedMemorySize, SM_NRM);
    cudaFuncSetAttribute((const void*)gemm_tc<128,128,4,2,false,3>,
                         cudaFuncAttributeMaxDynamicSharedMemorySize, SM_NRM);
    cudaFuncSetAttribute((const void*)gemm_tc<64,64,4,2,false,0>,
                         cudaFuncAttributeMaxDynamicSharedMemorySize, SM_PV);

    // q/k/v projections (tf32 tensor cores)
    gemm_tc<128,128,4,2,false,0><<<dim3(8,32,1),256,SM_NRM>>>(h, q_w, gq, nullptr, nullptr,
        NTOK, DMODEL, DMODEL, 1024,1024,1024,0, 0,0,0,0,0,0, 0);
    gemm_tc<128,128,4,2,false,0><<<dim3(8,32,1),256,SM_NRM>>>(h, k_w, gk, nullptr, nullptr,
        NTOK, DMODEL, DMODEL, 1024,1024,1024,0, 0,0,0,0,0,0, 0);
    gemm_tc<128,128,4,2,false,0><<<dim3(8,32,1),256,SM_NRM>>>(h, v_w, gv, nullptr, nullptr,
        NTOK, DMODEL, DMODEL, 1024,1024,1024,0, 0,0,0,0,0,0, 0);
    // relative projection: only rel rows <= 1087 are read -> rows [0, 4352) = 34 blocks
    gemm_tc<128,128,4,2,false,0><<<dim3(8,34,1),256,SM_NRM>>>(r, r_w, gkr, nullptr, nullptr,
        RTOK, DMODEL, DMODEL, 1024,1024,1024,0, 0,0,0,0,0,0, 0);

    ef_kernel<<<8192,256>>>(gq, rsb, se, gef);

    score_kernel<<<dim3(16,16,64),256,SCORE_SMEM>>>(gq, gk, gkr, rwb, rrb, gef, segm, msk, gs);
    softmax_kernel<<<8192,256>>>(gs);

    // attn_vec = P @ V, batched over (b,n), causal K-truncation (tf32)
    gemm_tc<64,64,4,2,false,0><<<dim3(1,16,64),256,SM_PV>>>(gs, gv, gav, nullptr, nullptr,
        1024, 64, 1024, 1024,4096,4096,0,
        16ll*1048576ll, 1048576ll, 1024ll, 64ll, 1024ll, 64ll, 1);

    // o-projection (B transposed) + residual h
    gemm_tc<128,128,4,2,true,2><<<dim3(8,32,1),256,SM_TRB>>>(gav, o_w, gpre, nullptr, h,
        NTOK, DMODEL, DMODEL, 1024,1024,1024,1024, 0,0,0,0,0,0, 0);
    ln_kernel<<<4096,256>>>(gpre, ln1g, ln1b, go1);

    // FF1 (+bias, exact GELU) and FF2 (+bias, +residual out1)
    gemm_tc<128,128,4,2,false,1><<<dim3(32,32,1),256,SM_NRM>>>(go1, w1, gffh, b1, nullptr,
        NTOK, DFF, DMODEL, 1024,4096,4096,0, 0,0,0,0,0,0, 0);
    gemm_tc<128,128,4,2,false,3><<<dim3(8,32,1),256,SM_NRM>>>(gffh, w2, gp2, b2, go1,
        NTOK, DMODEL, DFF, 4096,1024,1024,1024, 0,0,0,0,0,0, 0);
    ln_kernel<<<4096,256>>>(gp2, ln2g, ln2b, out);
}